// round 13
// baseline (speedup 1.0000x reference)
#include <cuda_runtime.h>
#include <cuda_fp16.h>
#include <stdint.h>

#define B_  16384
#define D_  4096
#define K_  14
#define QP  16

// ---- HMMA GEMM config: 128x128 CTA tile, 4 warps (2Mx2N), 64x64 warp tiles ----
#define BM 128
#define BN 128
#define BK 32
#define KTILES (D_ / BK)          // 128
#define ROWB 80                   // smem row stride bytes (32 halves + 8 pad)
#define A_STAGE (BM * ROWB)       // 10240 B
#define STAGE_BYTES (2 * A_STAGE) // A + B = 20480
#define NSTAGE 4
#define GEMM_SMEM (NSTAGE * STAGE_BYTES + 512)   // 82432 B -> 2 CTAs/SM

#define ND_CHUNK 512
#define NUM_SMEM (ND_CHUNK * QP * 4)  // 32768 B q-chunk

// ---------------- scratch (device globals; no allocations allowed) ----------
__device__ __half g_Xh [B_ * D_];
__device__ __half g_Th [B_ * D_];
__device__ __half g_Wvh[D_ * D_];
__device__ __half g_Wth[D_ * D_];
__device__ float g_phat [K_ * D_];
__device__ float g_qv   [D_ * QP];
__device__ float g_qt   [D_ * QP];
__device__ float g_cv   [K_];
__device__ float g_ct   [K_];
__device__ float g_normv[B_];
__device__ float g_normt[B_];
__device__ float g_numv [B_ * QP];
__device__ float g_numt [B_ * QP];
__device__ int   g_bcc  [K_ * K_];

// ---------------- helpers -----------------------------------------------------
__device__ __forceinline__ uint32_t smem_u32(const void* p) {
    return (uint32_t)__cvta_generic_to_shared(p);
}
__device__ __forceinline__ void cp16(uint32_t dst, const void* src) {
    asm volatile("cp.async.cg.shared.global [%0], [%1], 16;"
                 :: "r"(dst), "l"(src) : "memory");
}
__device__ __forceinline__ void cp_commit() {
    asm volatile("cp.async.commit_group;" ::: "memory");
}
template <int N>
__device__ __forceinline__ void cp_wait() {
    asm volatile("cp.async.wait_group %0;" :: "n"(N) : "memory");
}
__device__ __forceinline__ void ldsm_x4(uint32_t* r, uint32_t addr) {
    asm volatile("ldmatrix.sync.aligned.m8n8.x4.shared.b16 {%0,%1,%2,%3}, [%4];"
                 : "=r"(r[0]), "=r"(r[1]), "=r"(r[2]), "=r"(r[3]) : "r"(addr));
}
__device__ __forceinline__ void mma16816(float* c, const uint32_t* a, const uint32_t* b) {
    asm volatile(
        "mma.sync.aligned.m16n8k16.row.col.f32.f16.f16.f32 "
        "{%0,%1,%2,%3}, {%4,%5,%6,%7}, {%8,%9}, {%0,%1,%2,%3};"
        : "+f"(c[0]), "+f"(c[1]), "+f"(c[2]), "+f"(c[3])
        : "r"(a[0]), "r"(a[1]), "r"(a[2]), "r"(a[3]), "r"(b[0]), "r"(b[1]));
}

// ---------------- normalize prototypes + bias dots + ALL scratch zeroing ---------
__global__ void phat_kernel(const float* __restrict__ proto,
                            const float* __restrict__ bv,
                            const float* __restrict__ bt) {
    int k = blockIdx.x, tid = threadIdx.x;
    int gt = blockIdx.x * 256 + tid;                 // 3584 global threads
    for (int i = gt; i < D_ * QP; i += K_ * 256) { g_qv[i] = 0.f; g_qt[i] = 0.f; }
    for (int i = gt; i < B_ * QP; i += K_ * 256) { g_numv[i] = 0.f; g_numt[i] = 0.f; }
    for (int i = gt; i < B_; i += K_ * 256)      { g_normv[i] = 0.f; g_normt[i] = 0.f; }
    if (gt < K_ * K_) g_bcc[gt] = 0;

    float ss = 0.f, sv = 0.f, st = 0.f;
    for (int i = tid; i < D_; i += 256) {
        float p = proto[k * D_ + i];
        ss += p * p; sv += p * bv[i]; st += p * bt[i];
    }
    for (int off = 16; off; off >>= 1) {
        ss += __shfl_xor_sync(~0u, ss, off);
        sv += __shfl_xor_sync(~0u, sv, off);
        st += __shfl_xor_sync(~0u, st, off);
    }
    __shared__ float r0[8], r1[8], r2[8];
    __shared__ float s_inv;
    int warp = tid >> 5, lane = tid & 31;
    if (lane == 0) { r0[warp] = ss; r1[warp] = sv; r2[warp] = st; }
    __syncthreads();
    if (tid == 0) {
        float S = 0.f, V = 0.f, T = 0.f;
        for (int w = 0; w < 8; w++) { S += r0[w]; V += r1[w]; T += r2[w]; }
        float inv = 1.0f / fmaxf(sqrtf(S), 1e-12f);
        s_inv = inv;
        g_cv[k] = V * inv;
        g_ct[k] = T * inv;
    }
    __syncthreads();
    float inv = s_inv;
    for (int i = tid; i < D_; i += 256)
        g_phat[k * D_ + i] = proto[k * D_ + i] * inv;
}

// ---------------- q = W^T @ p_hat^T (fp32 exact) + W -> fp16 staging -------------
__global__ void q_kernel(const float* __restrict__ Wv, const float* __restrict__ Wt) {
    const float* W = blockIdx.z ? Wt : Wv;
    float* q = blockIdx.z ? g_qt : g_qv;
    __half* Wh = blockIdx.z ? g_Wth : g_Wvh;
    int i  = blockIdx.x * 256 + threadIdx.x;
    int j0 = blockIdx.y * 128;
    __shared__ float ps[K_][128];
    for (int idx = threadIdx.x; idx < K_ * 128; idx += 256) {
        int k = idx >> 7, j = idx & 127;
        ps[k][j] = g_phat[k * D_ + j0 + j];
    }
    __syncthreads();
    float acc[K_];
#pragma unroll
    for (int k = 0; k < K_; k++) acc[k] = 0.f;
#pragma unroll 4
    for (int jj = 0; jj < 128; ++jj) {
        float w = W[(size_t)(j0 + jj) * D_ + i];
        Wh[(size_t)(j0 + jj) * D_ + i] = __float2half_rn(w);
#pragma unroll
        for (int k = 0; k < K_; k++) acc[k] += w * ps[k][jj];
    }
#pragma unroll
    for (int k = 0; k < K_; k++) atomicAdd(&q[i * QP + k], acc[k]);
}

// ---------------- numerators v2: 4 rows/thread, 2-D grid, + X/T -> fp16 ----------
// grid (16, 8, 2): x -> 1024 b's, y -> 512 d's, z -> modality. 256 blocks.
// Each thread: 4 rows, 14 fp32 accumulators each; q chunk (512x16, 32KB) in smem,
// broadcast reads amortized over the 4 rows. Partial dots via atomicAdd.
__global__ void __launch_bounds__(256, 2)
num_kernel(const float* __restrict__ img, const float* __restrict__ txt) {
    const int z = blockIdx.z;
    const float* X = z ? txt : img;
    __half* Xh     = z ? g_Th : g_Xh;
    const float* q = z ? g_qt : g_qv;        // [D][QP]
    float* numOut  = z ? g_numt : g_numv;

    extern __shared__ float qs[];            // [ND_CHUNK][16]
    const int tid = threadIdx.x;
    const int b0 = blockIdx.x * 1024 + tid;  // rows b0 + r*256, r=0..3
    const int d0 = blockIdx.y * ND_CHUNK;

    {
        const float4* q4 = (const float4*)(q + (size_t)d0 * QP);
        float4* qs4 = (float4*)qs;
        for (int i = tid; i < ND_CHUNK * 4; i += 256) qs4[i] = q4[i];
    }
    __syncthreads();

    float acc[4][K_];
#pragma unroll
    for (int r = 0; r < 4; r++)
#pragma unroll
        for (int k = 0; k < K_; k++) acc[r][k] = 0.f;

    const float4* X4 = (const float4*)X;

    for (int it = 0; it < ND_CHUNK / 4; ++it) {     // 128 iters
        const int d4 = (d0 >> 2) + it;
        float4 xv[4];
#pragma unroll
        for (int r = 0; r < 4; r++)
            xv[r] = X4[(size_t)(b0 + r * 256) * (D_ / 4) + d4];

        // fold fp32 -> fp16 conversion of X/T (each element written exactly once)
#pragma unroll
        for (int r = 0; r < 4; r++) {
            __half2 h0 = __floats2half2_rn(xv[r].x, xv[r].y);
            __half2 h1 = __floats2half2_rn(xv[r].z, xv[r].w);
            uint2 o;
            o.x = *reinterpret_cast<uint32_t*>(&h0);
            o.y = *reinterpret_cast<uint32_t*>(&h1);
            *reinterpret_cast<uint2*>(Xh + (size_t)(b0 + r * 256) * D_ + d4 * 4) = o;
        }

        const float4* row = (const float4*)(qs + it * 64);   // 4 d-elems x 16 k
#pragma unroll
        for (int e = 0; e < 4; e++) {
            float4 q0 = row[e * 4 + 0];
            float4 q1 = row[e * 4 + 1];
            float4 q2 = row[e * 4 + 2];
            float4 q3 = row[e * 4 + 3];
            float qe[K_] = {q0.x, q0.y, q0.z, q0.w, q1.x, q1.y, q1.z, q1.w,
                            q2.x, q2.y, q2.z, q2.w, q3.x, q3.y};
#pragma unroll
            for (int r = 0; r < 4; r++) {
                float x = (e == 0) ? xv[r].x : (e == 1) ? xv[r].y
                        : (e == 2) ? xv[r].z : xv[r].w;
#pragma unroll
                for (int k = 0; k < K_; k++) acc[r][k] += x * qe[k];
            }
        }
    }

#pragma unroll
    for (int r = 0; r < 4; r++)
#pragma unroll
        for (int k = 0; k < K_; k++)
            atomicAdd(&numOut[(size_t)(b0 + r * 256) * QP + k], acc[r][k]);
}

// ---------------- HMMA GEMM: row norms of X @ W^T + bias (R11/R12, validated) ----
__global__ void __launch_bounds__(128, 2)
norm_gemm(const float* __restrict__ bv, const float* __restrict__ bt) {
    const int which = blockIdx.z;
    const __half* Xh = which ? g_Th : g_Xh;
    const __half* Wh = which ? g_Wth : g_Wvh;
    const float* bias = which ? bt : bv;
    float* normOut = which ? g_normt : g_normv;

    extern __shared__ __align__(128) char smem[];
    const uint32_t sbase = smem_u32(smem);
    float* sb = (float*)(smem + NSTAGE * STAGE_BYTES);

    const int tid  = threadIdx.x;
    const int lane = tid & 31;
    const int warp = tid >> 5;
    const int wm = warp & 1;
    const int wn = warp >> 1;
    const int m0 = blockIdx.y * BM;
    const int n0 = blockIdx.x * BN;

    sb[tid] = bias[n0 + tid];

    float acc[4][8][4];
#pragma unroll
    for (int mi = 0; mi < 4; mi++)
#pragma unroll
        for (int ni = 0; ni < 8; ni++)
#pragma unroll
            for (int c = 0; c < 4; c++) acc[mi][ni][c] = 0.f;

#define LOAD_STAGE(stage, kt)                                                  \
    {                                                                          \
        uint32_t base = sbase + (stage) * STAGE_BYTES;                         \
        int kb = (kt) * BK;                                                    \
        _Pragma("unroll")                                                      \
        for (int i = 0; i < 8; i++) {                                          \
            int idx = tid + i * 128;                                           \
            int r = (idx >> 2) & 127, c = idx & 3;                             \
            if (idx < 512)                                                     \
                cp16(base + r * ROWB + c * 16,                                 \
                     Xh + (size_t)(m0 + r) * D_ + kb + c * 8);                 \
            else                                                               \
                cp16(base + A_STAGE + r * ROWB + c * 16,                       \
                     Wh + (size_t)(n0 + r) * D_ + kb + c * 8);                 \
        }                                                                      \
        cp_commit();                                                           \
    }

    LOAD_STAGE(0, 0);
    LOAD_STAGE(1, 1);
    LOAD_STAGE(2, 2);

    const int a_r = wm * 64 + (lane & 15);
    const int a_c = (lane >> 4) << 3;
    const int b_r = wn * 64 + ((lane >> 4) << 3) + (lane & 7);
    const int b_c = ((lane >> 3) & 1) << 3;

    for (int kt = 0; kt < KTILES; ++kt) {
        cp_wait<2>();
        __syncthreads();

        const int st = kt & (NSTAGE - 1);
        const uint32_t aB = sbase + st * STAGE_BYTES;
        const uint32_t bB = aB + A_STAGE;

        uint32_t af[2][4][4], bf[2][4][4];
#pragma unroll
        for (int h = 0; h < 2; h++) {
            const int kk = h * 16;
#pragma unroll
            for (int mi = 0; mi < 4; mi++)
                ldsm_x4(af[h][mi], aB + (uint32_t)((a_r + mi * 16) * ROWB + (a_c + kk) * 2));
#pragma unroll
            for (int nj = 0; nj < 4; nj++)
                ldsm_x4(bf[h][nj], bB + (uint32_t)((b_r + nj * 16) * ROWB + (b_c + kk) * 2));
        }

        if (kt + 3 < KTILES) {
            LOAD_STAGE((kt + 3) & (NSTAGE - 1), kt + 3);
        } else {
            cp_commit();
        }

#pragma unroll
        for (int h = 0; h < 2; h++)
#pragma unroll
            for (int mi = 0; mi < 4; mi++)
#pragma unroll
                for (int nj = 0; nj < 4; nj++) {
                    mma16816(acc[mi][2 * nj],     af[h][mi], &bf[h][nj][0]);
                    mma16816(acc[mi][2 * nj + 1], af[h][mi], &bf[h][nj][2]);
                }
    }
#undef LOAD_STAGE

#pragma unroll
    for (int mi = 0; mi < 4; mi++) {
        float rs0 = 0.f, rs1 = 0.f;
#pragma unroll
        for (int ni = 0; ni < 8; ni++) {
            int nl = wn * 64 + ni * 8 + 2 * (lane & 3);
            float b0 = sb[nl], b1 = sb[nl + 1];
            float y0 = acc[mi][ni][0] + b0;
            float y1 = acc[mi][ni][1] + b1;
            float y2 = acc[mi][ni][2] + b0;
            float y3 = acc[mi][ni][3] + b1;
            rs0 += y0 * y0 + y1 * y1;
            rs1 += y2 * y2 + y3 * y3;
        }
        rs0 += __shfl_xor_sync(~0u, rs0, 1);
        rs0 += __shfl_xor_sync(~0u, rs0, 2);
        rs1 += __shfl_xor_sync(~0u, rs1, 1);
        rs1 += __shfl_xor_sync(~0u, rs1, 2);
        if ((lane & 3) == 0) {
            int row = m0 + wm * 64 + mi * 16 + (lane >> 2);
            atomicAdd(&normOut[row], rs0);
            atomicAdd(&normOut[row + 8], rs1);
        }
    }
}

// ---------------- batch co-occurrence counts --------------------------------------
__global__ void bcc_kernel(const int* __restrict__ labels) {
    __shared__ unsigned s_mask[256];
    int b = blockIdx.x * 256 + threadIdx.x;
    unsigned m = 0;
#pragma unroll
    for (int k = 0; k < K_; k++) m |= (labels[(size_t)b * K_ + k] != 0 ? 1u : 0u) << k;
    s_mask[threadIdx.x] = m;
    __syncthreads();
    if (threadIdx.x < K_ * K_) {
        int i = threadIdx.x / K_, j = threadIdx.x % K_;
        int cnt = 0;
        for (int r = 0; r < 256; ++r) {
            unsigned mm = s_mask[r];
            cnt += (int)(((mm >> i) & 1u) & ((mm >> j) & 1u));
        }
        atomicAdd(&g_bcc[threadIdx.x], cnt);
    }
}

// ---------------- finalize: shapley = 0.5*((numv+cv)/nv + (numt+ct)/nt)*label -----
__global__ void finalize_kernel(const int* __restrict__ labels, float* __restrict__ out) {
    int idx = blockIdx.x * 256 + threadIdx.x;
    if (idx >= B_ * K_) return;
    int b = idx / K_, k = idx - b * K_;
    float nv = sqrtf(g_normv[b]);
    float nt = sqrtf(g_normt[b]);
    float vs = (g_numv[(size_t)b * QP + k] + g_cv[k]) / fmaxf(nv, 1e-12f);
    float ts = (g_numt[(size_t)b * QP + k] + g_ct[k]) / fmaxf(nt, 1e-12f);
    out[idx] = 0.5f * (vs + ts) * (float)labels[idx];
}

// ---------------- cooccur loss + prototype passthrough ------------------------------
__global__ void loss_kernel(const float* __restrict__ coocc, float* __restrict__ out_loss) {
    int t = threadIdx.x;
    float d = 0.f;
    if (t < K_ * K_) {
        float bc = (float)g_bcc[t] / (float)B_;
        float sg = 1.0f / (1.0f + expf(-coocc[t]));
        float e = sg - bc;
        d = e * e;
    }
    for (int off = 16; off; off >>= 1) d += __shfl_xor_sync(~0u, d, off);
    __shared__ float r[8];
    int warp = t >> 5, lane = t & 31;
    if (lane == 0) r[warp] = d;
    __syncthreads();
    if (t == 0) {
        float S = 0.f;
        for (int w = 0; w < 8; w++) S += r[w];
        out_loss[0] = S / (float)(K_ * K_);
    }
}

__global__ void copy_proto_kernel(const float* __restrict__ proto, float* __restrict__ dst) {
    int idx = blockIdx.x * blockDim.x + threadIdx.x;
    if (idx < K_ * D_) dst[idx] = proto[idx];
}

// ---------------- launch --------------------------------------------------------------
extern "C" void kernel_launch(void* const* d_in, const int* in_sizes, int n_in,
                              void* d_out, int out_size) {
    const float* img    = (const float*)d_in[0];
    const float* txt    = (const float*)d_in[1];
    const int*   labels = (const int*)d_in[2];
    const float* Wv     = (const float*)d_in[3];
    const float* bv     = (const float*)d_in[4];
    const float* Wt     = (const float*)d_in[5];
    const float* bt     = (const float*)d_in[6];
    const float* proto  = (const float*)d_in[7];
    const float* coocc  = (const float*)d_in[8];
    float* out = (float*)d_out;

    cudaFuncSetAttribute(norm_gemm, cudaFuncAttributeMaxDynamicSharedMemorySize,
                         GEMM_SMEM);
    cudaFuncSetAttribute(num_kernel, cudaFuncAttributeMaxDynamicSharedMemorySize,
                         NUM_SMEM);

    phat_kernel<<<K_, 256>>>(proto, bv, bt);                 // 1: phat + all zeroing
    q_kernel<<<dim3(16, 32, 2), 256>>>(Wv, Wt);              // 2: q + W->fp16
    num_kernel<<<dim3(16, 8, 2), 256, NUM_SMEM>>>(img, txt); // 3: numerators + X/T->fp16

    dim3 ggrid(D_ / BN, B_ / BM, 2);   // (32, 128, 2): both GEMMs
    norm_gemm<<<ggrid, 128, GEMM_SMEM>>>(bv, bt);            // 4

    bcc_kernel<<<B_ / 256, 256>>>(labels);                   // 5
    finalize_kernel<<<(B_ * K_ + 255) / 256, 256>>>(labels, out);    // 6

    if (out_size >= B_ * K_ + K_ * D_ + 1) {
        copy_proto_kernel<<<(K_ * D_ + 255) / 256, 256>>>(proto, out + (size_t)B_ * K_);
        loss_kernel<<<1, 256>>>(coocc, out + (size_t)B_ * K_ + (size_t)K_ * D_);
    }
}

// round 14
// speedup vs baseline: 1.0348x; 1.0348x over previous
#include <cuda_runtime.h>
#include <cuda_fp16.h>
#include <stdint.h>

#define B_  16384
#define D_  4096
#define K_  14
#define QP  16

// ---- HMMA GEMM config: 128x128 CTA tile, 4 warps (2Mx2N), 64x64 warp tiles ----
#define BM 128
#define BN 128
#define BK 32
#define KTILES (D_ / BK)          // 128
#define ROWB 80                   // smem row stride bytes (32 halves + 8 pad)
#define A_STAGE (BM * ROWB)       // 10240 B
#define STAGE_BYTES (2 * A_STAGE) // A + B = 20480
#define NSTAGE 4
#define GEMM_SMEM (NSTAGE * STAGE_BYTES + 512)   // 82432 B -> 2 CTAs/SM

#define NUM_SMEM (2048 * 16 * 4)  // 131072 B q-chunk for num_kernel

// ---------------- scratch (device globals; no allocations allowed) ----------
__device__ __half g_Xh [B_ * D_];
__device__ __half g_Th [B_ * D_];
__device__ __half g_Wvh[D_ * D_];
__device__ __half g_Wth[D_ * D_];
__device__ float g_phat [K_ * D_];
__device__ float g_qv   [D_ * QP];
__device__ float g_qt   [D_ * QP];
__device__ float g_cv   [K_];
__device__ float g_ct   [K_];
__device__ float g_normv[B_];
__device__ float g_normt[B_];
__device__ float g_numv [B_ * QP];
__device__ float g_numt [B_ * QP];
__device__ int   g_bcc  [K_ * K_];

// ---------------- helpers -----------------------------------------------------
__device__ __forceinline__ uint32_t smem_u32(const void* p) {
    return (uint32_t)__cvta_generic_to_shared(p);
}
__device__ __forceinline__ void cp16(uint32_t dst, const void* src) {
    asm volatile("cp.async.cg.shared.global [%0], [%1], 16;"
                 :: "r"(dst), "l"(src) : "memory");
}
__device__ __forceinline__ void cp_commit() {
    asm volatile("cp.async.commit_group;" ::: "memory");
}
template <int N>
__device__ __forceinline__ void cp_wait() {
    asm volatile("cp.async.wait_group %0;" :: "n"(N) : "memory");
}
__device__ __forceinline__ void ldsm_x4(uint32_t* r, uint32_t addr) {
    asm volatile("ldmatrix.sync.aligned.m8n8.x4.shared.b16 {%0,%1,%2,%3}, [%4];"
                 : "=r"(r[0]), "=r"(r[1]), "=r"(r[2]), "=r"(r[3]) : "r"(addr));
}
__device__ __forceinline__ void mma16816(float* c, const uint32_t* a, const uint32_t* b) {
    asm volatile(
        "mma.sync.aligned.m16n8k16.row.col.f32.f16.f16.f32 "
        "{%0,%1,%2,%3}, {%4,%5,%6,%7}, {%8,%9}, {%0,%1,%2,%3};"
        : "+f"(c[0]), "+f"(c[1]), "+f"(c[2]), "+f"(c[3])
        : "r"(a[0]), "r"(a[1]), "r"(a[2]), "r"(a[3]), "r"(b[0]), "r"(b[1]));
}

// ---------------- normalize prototypes + bias dots + scratch zeroing -------------
__global__ void phat_kernel(const float* __restrict__ proto,
                            const float* __restrict__ bv,
                            const float* __restrict__ bt) {
    int k = blockIdx.x, tid = threadIdx.x;
    for (int i = blockIdx.x * 256 + tid; i < D_ * QP; i += K_ * 256) {
        g_qv[i] = 0.f; g_qt[i] = 0.f;
    }
    if (blockIdx.x == 0 && tid < K_ * K_) g_bcc[tid] = 0;

    float ss = 0.f, sv = 0.f, st = 0.f;
    for (int i = tid; i < D_; i += 256) {
        float p = proto[k * D_ + i];
        ss += p * p; sv += p * bv[i]; st += p * bt[i];
    }
    for (int off = 16; off; off >>= 1) {
        ss += __shfl_xor_sync(~0u, ss, off);
        sv += __shfl_xor_sync(~0u, sv, off);
        st += __shfl_xor_sync(~0u, st, off);
    }
    __shared__ float r0[8], r1[8], r2[8];
    __shared__ float s_inv;
    int warp = tid >> 5, lane = tid & 31;
    if (lane == 0) { r0[warp] = ss; r1[warp] = sv; r2[warp] = st; }
    __syncthreads();
    if (tid == 0) {
        float S = 0.f, V = 0.f, T = 0.f;
        for (int w = 0; w < 8; w++) { S += r0[w]; V += r1[w]; T += r2[w]; }
        float inv = 1.0f / fmaxf(sqrtf(S), 1e-12f);
        s_inv = inv;
        g_cv[k] = V * inv;
        g_ct[k] = T * inv;
    }
    __syncthreads();
    float inv = s_inv;
    for (int i = tid; i < D_; i += 256)
        g_phat[k * D_ + i] = proto[k * D_ + i] * inv;
}

// ---------------- q = W^T @ p_hat^T (fp32 exact) + W -> fp16 staging -------------
__global__ void q_kernel(const float* __restrict__ Wv, const float* __restrict__ Wt) {
    const float* W = blockIdx.z ? Wt : Wv;
    float* q = blockIdx.z ? g_qt : g_qv;
    __half* Wh = blockIdx.z ? g_Wth : g_Wvh;
    int i  = blockIdx.x * 256 + threadIdx.x;
    int j0 = blockIdx.y * 128;
    __shared__ float ps[K_][128];
    for (int idx = threadIdx.x; idx < K_ * 128; idx += 256) {
        int k = idx >> 7, j = idx & 127;
        ps[k][j] = g_phat[k * D_ + j0 + j];
    }
    __syncthreads();
    float acc[K_];
#pragma unroll
    for (int k = 0; k < K_; k++) acc[k] = 0.f;
#pragma unroll 4
    for (int jj = 0; jj < 128; ++jj) {
        float w = W[(size_t)(j0 + jj) * D_ + i];
        Wh[(size_t)(j0 + jj) * D_ + i] = __float2half_rn(w);
#pragma unroll
        for (int k = 0; k < K_; k++) acc[k] += w * ps[k][jj];
    }
#pragma unroll
    for (int k = 0; k < K_; k++) atomicAdd(&q[i * QP + k], acc[k]);
}

// ---------------- numerators (R12 v1, validated 317us) + folded X/T -> fp16 ------
// q-stationary: 128-KB q chunk in smem, broadcast LDS; thread owns one row b.
// Also zeros the norm accumulators for the GEMM and writes the fp16 copy of X/T.
__global__ void __launch_bounds__(256, 1)
num_kernel(const float* __restrict__ img, const float* __restrict__ txt) {
    const int z = blockIdx.y;
    const float* X = z ? txt : img;
    __half* Xh     = z ? g_Th : g_Xh;
    const float* q = z ? g_qt : g_qv;        // [D][QP]
    const float* cc = z ? g_ct : g_cv;
    float* numOut  = z ? g_numt : g_numv;
    float* normOut = z ? g_normt : g_normv;

    extern __shared__ float qs[];            // [2048][16]
    const int tid = threadIdx.x;
    const int b = blockIdx.x * 256 + tid;

    normOut[b] = 0.f;

    float acc[K_];
#pragma unroll
    for (int k = 0; k < K_; k++) acc[k] = 0.f;

    const float4* X4 = (const float4*)X;
    float4* qs4 = (float4*)qs;

    for (int c = 0; c < 2; c++) {
        __syncthreads();                     // all readers done with prev chunk
        const float4* q4 = (const float4*)(q + c * 2048 * QP);
        for (int i = tid; i < 2048 * 4; i += 256) qs4[i] = q4[i];
        __syncthreads();

        size_t xbase = (size_t)b * (D_ / 4) + c * 512;
        for (int it = 0; it < 512; ++it) {
            float4 xv = X4[xbase + it];

            // folded fp32 -> fp16 conversion (each element written exactly once)
            {
                __half2 h0 = __floats2half2_rn(xv.x, xv.y);
                __half2 h1 = __floats2half2_rn(xv.z, xv.w);
                uint2 o;
                o.x = *reinterpret_cast<uint32_t*>(&h0);
                o.y = *reinterpret_cast<uint32_t*>(&h1);
                *reinterpret_cast<uint2*>(Xh + ((xbase + it) << 2)) = o;
            }

            const float4* row = (const float4*)(qs + it * 64);  // 4 rows x 16
            float xe[4] = {xv.x, xv.y, xv.z, xv.w};
#pragma unroll
            for (int e = 0; e < 4; e++) {
                float4 q0 = row[e * 4 + 0];
                float4 q1 = row[e * 4 + 1];
                float4 q2 = row[e * 4 + 2];
                float4 q3 = row[e * 4 + 3];
                float x = xe[e];
                acc[0]  += x * q0.x; acc[1]  += x * q0.y;
                acc[2]  += x * q0.z; acc[3]  += x * q0.w;
                acc[4]  += x * q1.x; acc[5]  += x * q1.y;
                acc[6]  += x * q1.z; acc[7]  += x * q1.w;
                acc[8]  += x * q2.x; acc[9]  += x * q2.y;
                acc[10] += x * q2.z; acc[11] += x * q2.w;
                acc[12] += x * q3.x; acc[13] += x * q3.y;
            }
        }
    }

    float v[QP];
#pragma unroll
    for (int k = 0; k < K_; k++) v[k] = acc[k] + cc[k];
    v[14] = 0.f; v[15] = 0.f;
    float4* o4 = (float4*)(numOut + (size_t)b * QP);
#pragma unroll
    for (int j = 0; j < 4; j++)
        o4[j] = make_float4(v[j * 4], v[j * 4 + 1], v[j * 4 + 2], v[j * 4 + 3]);
}

// ---------------- HMMA GEMM: row norms of X @ W^T + bias (R11/R12, validated) ----
__global__ void __launch_bounds__(128, 2)
norm_gemm(const float* __restrict__ bv, const float* __restrict__ bt) {
    const int which = blockIdx.z;
    const __half* Xh = which ? g_Th : g_Xh;
    const __half* Wh = which ? g_Wth : g_Wvh;
    const float* bias = which ? bt : bv;
    float* normOut = which ? g_normt : g_normv;

    extern __shared__ __align__(128) char smem[];
    const uint32_t sbase = smem_u32(smem);
    float* sb = (float*)(smem + NSTAGE * STAGE_BYTES);

    const int tid  = threadIdx.x;
    const int lane = tid & 31;
    const int warp = tid >> 5;
    const int wm = warp & 1;
    const int wn = warp >> 1;
    const int m0 = blockIdx.y * BM;
    const int n0 = blockIdx.x * BN;

    sb[tid] = bias[n0 + tid];

    float acc[4][8][4];
#pragma unroll
    for (int mi = 0; mi < 4; mi++)
#pragma unroll
        for (int ni = 0; ni < 8; ni++)
#pragma unroll
            for (int c = 0; c < 4; c++) acc[mi][ni][c] = 0.f;

#define LOAD_STAGE(stage, kt)                                                  \
    {                                                                          \
        uint32_t base = sbase + (stage) * STAGE_BYTES;                         \
        int kb = (kt) * BK;                                                    \
        _Pragma("unroll")                                                      \
        for (int i = 0; i < 8; i++) {                                          \
            int idx = tid + i * 128;                                           \
            int r = (idx >> 2) & 127, c = idx & 3;                             \
            if (idx < 512)                                                     \
                cp16(base + r * ROWB + c * 16,                                 \
                     Xh + (size_t)(m0 + r) * D_ + kb + c * 8);                 \
            else                                                               \
                cp16(base + A_STAGE + r * ROWB + c * 16,                       \
                     Wh + (size_t)(n0 + r) * D_ + kb + c * 8);                 \
        }                                                                      \
        cp_commit();                                                           \
    }

    LOAD_STAGE(0, 0);
    LOAD_STAGE(1, 1);
    LOAD_STAGE(2, 2);

    const int a_r = wm * 64 + (lane & 15);
    const int a_c = (lane >> 4) << 3;
    const int b_r = wn * 64 + ((lane >> 4) << 3) + (lane & 7);
    const int b_c = ((lane >> 3) & 1) << 3;

    for (int kt = 0; kt < KTILES; ++kt) {
        cp_wait<2>();
        __syncthreads();

        const int st = kt & (NSTAGE - 1);
        const uint32_t aB = sbase + st * STAGE_BYTES;
        const uint32_t bB = aB + A_STAGE;

        uint32_t af[2][4][4], bf[2][4][4];
#pragma unroll
        for (int h = 0; h < 2; h++) {
            const int kk = h * 16;
#pragma unroll
            for (int mi = 0; mi < 4; mi++)
                ldsm_x4(af[h][mi], aB + (uint32_t)((a_r + mi * 16) * ROWB + (a_c + kk) * 2));
#pragma unroll
            for (int nj = 0; nj < 4; nj++)
                ldsm_x4(bf[h][nj], bB + (uint32_t)((b_r + nj * 16) * ROWB + (b_c + kk) * 2));
        }

        if (kt + 3 < KTILES) {
            LOAD_STAGE((kt + 3) & (NSTAGE - 1), kt + 3);
        } else {
            cp_commit();
        }

#pragma unroll
        for (int h = 0; h < 2; h++)
#pragma unroll
            for (int mi = 0; mi < 4; mi++)
#pragma unroll
                for (int nj = 0; nj < 4; nj++) {
                    mma16816(acc[mi][2 * nj],     af[h][mi], &bf[h][nj][0]);
                    mma16816(acc[mi][2 * nj + 1], af[h][mi], &bf[h][nj][2]);
                }
    }
#undef LOAD_STAGE

#pragma unroll
    for (int mi = 0; mi < 4; mi++) {
        float rs0 = 0.f, rs1 = 0.f;
#pragma unroll
        for (int ni = 0; ni < 8; ni++) {
            int nl = wn * 64 + ni * 8 + 2 * (lane & 3);
            float b0 = sb[nl], b1 = sb[nl + 1];
            float y0 = acc[mi][ni][0] + b0;
            float y1 = acc[mi][ni][1] + b1;
            float y2 = acc[mi][ni][2] + b0;
            float y3 = acc[mi][ni][3] + b1;
            rs0 += y0 * y0 + y1 * y1;
            rs1 += y2 * y2 + y3 * y3;
        }
        rs0 += __shfl_xor_sync(~0u, rs0, 1);
        rs0 += __shfl_xor_sync(~0u, rs0, 2);
        rs1 += __shfl_xor_sync(~0u, rs1, 1);
        rs1 += __shfl_xor_sync(~0u, rs1, 2);
        if ((lane & 3) == 0) {
            int row = m0 + wm * 64 + mi * 16 + (lane >> 2);
            atomicAdd(&normOut[row], rs0);
            atomicAdd(&normOut[row + 8], rs1);
        }
    }
}

// ---------------- batch co-occurrence counts --------------------------------------
__global__ void bcc_kernel(const int* __restrict__ labels) {
    __shared__ unsigned s_mask[256];
    int b = blockIdx.x * 256 + threadIdx.x;
    unsigned m = 0;
#pragma unroll
    for (int k = 0; k < K_; k++) m |= (labels[(size_t)b * K_ + k] != 0 ? 1u : 0u) << k;
    s_mask[threadIdx.x] = m;
    __syncthreads();
    if (threadIdx.x < K_ * K_) {
        int i = threadIdx.x / K_, j = threadIdx.x % K_;
        int cnt = 0;
        for (int r = 0; r < 256; ++r) {
            unsigned mm = s_mask[r];
            cnt += (int)(((mm >> i) & 1u) & ((mm >> j) & 1u));
        }
        atomicAdd(&g_bcc[threadIdx.x], cnt);
    }
}

// ---------------- finalize: shapley = 0.5*(numv/nv + numt/nt)*label ---------------
__global__ void finalize_kernel(const int* __restrict__ labels, float* __restrict__ out) {
    int idx = blockIdx.x * 256 + threadIdx.x;
    if (idx >= B_ * K_) return;
    int b = idx / K_, k = idx - b * K_;
    float nv = sqrtf(g_normv[b]);
    float nt = sqrtf(g_normt[b]);
    float vs = g_numv[(size_t)b * QP + k] / fmaxf(nv, 1e-12f);
    float ts = g_numt[(size_t)b * QP + k] / fmaxf(nt, 1e-12f);
    out[idx] = 0.5f * (vs + ts) * (float)labels[idx];
}

// ---------------- cooccur loss + prototype passthrough ------------------------------
__global__ void loss_kernel(const float* __restrict__ coocc, float* __restrict__ out_loss) {
    int t = threadIdx.x;
    float d = 0.f;
    if (t < K_ * K_) {
        float bc = (float)g_bcc[t] / (float)B_;
        float sg = 1.0f / (1.0f + expf(-coocc[t]));
        float e = sg - bc;
        d = e * e;
    }
    for (int off = 16; off; off >>= 1) d += __shfl_xor_sync(~0u, d, off);
    __shared__ float r[8];
    int warp = t >> 5, lane = t & 31;
    if (lane == 0) r[warp] = d;
    __syncthreads();
    if (t == 0) {
        float S = 0.f;
        for (int w = 0; w < 8; w++) S += r[w];
        out_loss[0] = S / (float)(K_ * K_);
    }
}

__global__ void copy_proto_kernel(const float* __restrict__ proto, float* __restrict__ dst) {
    int idx = blockIdx.x * blockDim.x + threadIdx.x;
    if (idx < K_ * D_) dst[idx] = proto[idx];
}

// ---------------- launch --------------------------------------------------------------
extern "C" void kernel_launch(void* const* d_in, const int* in_sizes, int n_in,
                              void* d_out, int out_size) {
    const float* img    = (const float*)d_in[0];
    const float* txt    = (const float*)d_in[1];
    const int*   labels = (const int*)d_in[2];
    const float* Wv     = (const float*)d_in[3];
    const float* bv     = (const float*)d_in[4];
    const float* Wt     = (const float*)d_in[5];
    const float* bt     = (const float*)d_in[6];
    const float* proto  = (const float*)d_in[7];
    const float* coocc  = (const float*)d_in[8];
    float* out = (float*)d_out;

    cudaFuncSetAttribute(norm_gemm, cudaFuncAttributeMaxDynamicSharedMemorySize,
                         GEMM_SMEM);
    cudaFuncSetAttribute(num_kernel, cudaFuncAttributeMaxDynamicSharedMemorySize,
                         NUM_SMEM);

    phat_kernel<<<K_, 256>>>(proto, bv, bt);                 // 1: phat + zeroing
    q_kernel<<<dim3(16, 32, 2), 256>>>(Wv, Wt);              // 2: q + W->fp16
    num_kernel<<<dim3(B_ / 256, 2), 256, NUM_SMEM>>>(img, txt); // 3: num + X/T->fp16 + norm zero

    dim3 ggrid(D_ / BN, B_ / BM, 2);   // (32, 128, 2): both GEMMs
    norm_gemm<<<ggrid, 128, GEMM_SMEM>>>(bv, bt);            // 4

    bcc_kernel<<<B_ / 256, 256>>>(labels);                   // 5
    finalize_kernel<<<(B_ * K_ + 255) / 256, 256>>>(labels, out);    // 6

    if (out_size >= B_ * K_ + K_ * D_ + 1) {
        copy_proto_kernel<<<(K_ * D_ + 255) / 256, 256>>>(proto, out + (size_t)B_ * K_);
        loss_kernel<<<1, 256>>>(coocc, out + (size_t)B_ * K_ + (size_t)K_ * D_);
    }
}